// round 1
// baseline (speedup 1.0000x reference)
#include <cuda_runtime.h>
#include <math.h>

#define B_   64
#define NI_  2048
#define DI_  8
#define NC_  32
#define DC_  16

// Scratch (device globals; allocation-free per harness rules).
// g_u layout: [b][i][d][c]  -> idx = ((b*NI + i)*DC + d)*NC + c  (coalesced over c)
__device__ float g_u[(long long)B_ * NI_ * DC_ * NC_];   // 256 MB fp32
__device__ float g_s[B_ * NC_ * DC_];                    // [b][c][d], must be zero between passes
__device__ float g_v[2][B_ * NC_ * DC_];                 // v1, v2

// ---------------------------------------------------------------------------
// K_u: one block per input capsule i. Computes u[b,i,d,c] = sum_f x[b,i,f]*W[c,i,d,f]
// W[:,i,:,:] staged in shared as [(d*DI+f)*NC + c] (conflict-free lane=c reads).
// ---------------------------------------------------------------------------
__global__ __launch_bounds__(256) void k_u(const float* __restrict__ x,
                                           const float* __restrict__ W) {
    __shared__ __align__(16) float W_sh[DC_ * DI_ * NC_];  // 16 KB
    __shared__ __align__(16) float x_sh[B_ * DI_];         // 2 KB

    const int i = blockIdx.x;
    const int t = threadIdx.x;

    // Load W[:, i, :, :]: per c a contiguous run of 128 floats (d,f).
    {
        const int c = t >> 3;        // 0..31
        const int part = t & 7;      // 0..7
        const float* Wg = W + ((long long)c * NI_ + i) * (DC_ * DI_);
        #pragma unroll
        for (int q = 0; q < 16; q++) {
            const int df = part * 16 + q;      // 0..127
            W_sh[df * NC_ + c] = Wg[df];
        }
    }
    // Load x[:, i, :]
    if (t < B_ * 2) {
        const int b = t >> 1;
        const int h = (t & 1) * 4;
        const float4 v = *(const float4*)(x + ((long long)b * NI_ + i) * DI_ + h);
        x_sh[b * DI_ + h + 0] = v.x;
        x_sh[b * DI_ + h + 1] = v.y;
        x_sh[b * DI_ + h + 2] = v.z;
        x_sh[b * DI_ + h + 3] = v.w;
    }
    __syncthreads();

    const int w = t >> 5;        // warp id -> d0
    const int c = t & 31;        // lane -> output capsule
    const int d0 = w, d1 = w + 8;

    float W0[DI_], W1[DI_];
    #pragma unroll
    for (int f = 0; f < DI_; f++) {
        W0[f] = W_sh[(d0 * DI_ + f) * NC_ + c];
        W1[f] = W_sh[(d1 * DI_ + f) * NC_ + c];
    }

    #pragma unroll 4
    for (int b = 0; b < B_; b++) {
        const float4 xa = *(const float4*)&x_sh[b * DI_];
        const float4 xb = *(const float4*)&x_sh[b * DI_ + 4];
        float a0 = xa.x * W0[0] + xa.y * W0[1] + xa.z * W0[2] + xa.w * W0[3]
                 + xb.x * W0[4] + xb.y * W0[5] + xb.z * W0[6] + xb.w * W0[7];
        float a1 = xa.x * W1[0] + xa.y * W1[1] + xa.z * W1[2] + xa.w * W1[3]
                 + xb.x * W1[4] + xb.y * W1[5] + xb.z * W1[6] + xb.w * W1[7];
        const long long base = ((long long)b * NI_ + i) * DC_;
        g_u[(base + d0) * NC_ + c] = a0;
        g_u[(base + d1) * NC_ + c] = a1;
    }
}

// ---------------------------------------------------------------------------
// K_route<NPREV>: one fused pass over u.
//   logits[c] = NI * sum_k <u, v_k>   (k over previous iterations; NPREV=0 -> uniform)
//   coef      = softmax_c(logits)
//   s[b,c,:] += coef * u
// lane = c; agree is an in-lane dot; softmax is a 32-lane warp reduction.
// ---------------------------------------------------------------------------
template <int NPREV>
__global__ __launch_bounds__(256) void k_route() {
    __shared__ float s_sh[8 * NC_ * DC_];  // [warp][d*32+c], 16 KB

    const int CH = 8;                       // i-chunks per b
    const int b = blockIdx.x / CH;
    const int chunk = blockIdx.x % CH;
    const int w = threadIdx.x >> 5;
    const int c = threadIdx.x & 31;
    const int IPW = NI_ / CH / 8;           // 32 i per warp
    const int i0 = chunk * (NI_ / CH) + w * IPW;

    float v1[DC_], v2[DC_];
    if (NPREV >= 1) {
        #pragma unroll
        for (int d = 0; d < DC_; d++) v1[d] = g_v[0][(b * NC_ + c) * DC_ + d];
    }
    if (NPREV >= 2) {
        #pragma unroll
        for (int d = 0; d < DC_; d++) v2[d] = g_v[1][(b * NC_ + c) * DC_ + d];
    }

    float s_acc[DC_];
    #pragma unroll
    for (int d = 0; d < DC_; d++) s_acc[d] = 0.0f;

    for (int i = i0; i < i0 + IPW; i++) {
        const float* up = g_u + ((long long)b * NI_ + i) * (DC_ * NC_);
        float u[DC_];
        #pragma unroll
        for (int d = 0; d < DC_; d++) u[d] = up[d * NC_ + c];   // coalesced 128B/instr

        float coef;
        if (NPREV == 0) {
            coef = 1.0f;   // uniform coupling; 1/NC applied in squash scale
        } else {
            float a = 0.0f;
            #pragma unroll
            for (int d = 0; d < DC_; d++) a += u[d] * v1[d];
            if (NPREV >= 2) {
                #pragma unroll
                for (int d = 0; d < DC_; d++) a += u[d] * v2[d];
            }
            float logit = (float)NI_ * a;
            float m = logit;
            #pragma unroll
            for (int off = 16; off > 0; off >>= 1)
                m = fmaxf(m, __shfl_xor_sync(0xFFFFFFFFu, m, off));
            float e = __expf(logit - m);
            float sum = e;
            #pragma unroll
            for (int off = 16; off > 0; off >>= 1)
                sum += __shfl_xor_sync(0xFFFFFFFFu, sum, off);
            coef = e / sum;
        }
        #pragma unroll
        for (int d = 0; d < DC_; d++) s_acc[d] = fmaf(coef, u[d], s_acc[d]);
    }

    // Block reduction: warp partials -> shared [w][d*32+c] (lane-stride-1 stores)
    #pragma unroll
    for (int d = 0; d < DC_; d++) s_sh[w * (NC_ * DC_) + d * NC_ + c] = s_acc[d];
    __syncthreads();

    // 512 values; 256 threads each reduce 2, then atomicAdd to g_s
    #pragma unroll
    for (int r = 0; r < 2; r++) {
        const int idx = threadIdx.x + r * 256;      // d*32 + c
        float acc = 0.0f;
        #pragma unroll
        for (int ww = 0; ww < 8; ww++) acc += s_sh[ww * (NC_ * DC_) + idx];
        const int cc = idx & 31, dd = idx >> 5;
        atomicAdd(&g_s[(b * NC_ + cc) * DC_ + dd], acc);
    }
}

// ---------------------------------------------------------------------------
// Squash: v = (|s|^2/(1+|s|^2)) * s / sqrt(|s|^2 + 1e-7). One thread per (b,c).
// Also zeroes g_s so the next route pass (and the next graph replay) start clean.
// ---------------------------------------------------------------------------
__global__ void k_squash(int dst_idx, float* __restrict__ dout, float scale) {
    const int t = blockIdx.x * blockDim.x + threadIdx.x;
    if (t >= B_ * NC_) return;
    float* sp = g_s + t * DC_;
    float s[DC_];
    float sq = 0.0f;
    #pragma unroll
    for (int d = 0; d < DC_; d++) {
        s[d] = sp[d] * scale;
        sq += s[d] * s[d];
        sp[d] = 0.0f;   // reset accumulator
    }
    const float fac = (sq / (1.0f + sq)) * rsqrtf(sq + 1e-7f) * (sqrtf(sq + 1e-7f) * rsqrtf(sq + 1e-7f)); // == (sq/(1+sq))/sqrt(sq+eps)
    const float f2 = (sq / (1.0f + sq)) / sqrtf(sq + 1e-7f);
    float* vp = (dst_idx >= 0) ? (g_v[dst_idx] + t * DC_) : (dout + t * DC_);
    #pragma unroll
    for (int d = 0; d < DC_; d++) vp[d] = s[d] * f2;
    (void)fac;
}

// ---------------------------------------------------------------------------
extern "C" void kernel_launch(void* const* d_in, const int* in_sizes, int n_in,
                              void* d_out, int out_size) {
    const float* x = (const float*)d_in[0];
    const float* W = (const float*)d_in[1];
    if (n_in >= 2 && in_sizes[0] == NC_ * NI_ * DC_ * DI_) {  // defensive: swap if order differs
        const float* tmp = x; x = W; W = tmp;
    }
    float* out = (float*)d_out;

    k_u<<<NI_, 256>>>(x, W);

    // iter 1: uniform coupling
    k_route<0><<<B_ * 8, 256>>>();
    k_squash<<<8, 256>>>(0, nullptr, 1.0f / (float)NC_);

    // iter 2: logits = NI*<u,v1>
    k_route<1><<<B_ * 8, 256>>>();
    k_squash<<<8, 256>>>(1, nullptr, 1.0f);

    // iter 3: logits = NI*(<u,v1> + <u,v2>), output v3
    k_route<2><<<B_ * 8, 256>>>();
    k_squash<<<8, 256>>>(-1, out, 1.0f);
}